// round 14
// baseline (speedup 1.0000x reference)
#include <cuda_runtime.h>
#include <cuda_fp16.h>
#include <cstdint>

#define LOG2E 1.4426950408889634f

// ---------------- scratch (device globals; no allocations allowed) ----------
__device__ float    g_part[8 * 64];           // per (b,c) partial sums
__device__ float    g_t[64];                  // relu(MLP) * log2(e)
__device__ uint32_t g_Wh[64 * 25 * 8];        // half2 weights [c][tap][8 slots]
__device__ float    g_bc[9 * 25];             // per-tap bias [k][tap]
__device__ float    g_B[225];                 // bias case table [k][hcase][wcase]
__device__ float    g_wt[8 * 9 * 128 * 128];  // conv logits [b][k][h][w]

__device__ __forceinline__ __half2 u2h(uint32_t u) {
    return *reinterpret_cast<__half2*>(&u);
}

// ---------------- chansum: 512 blocks, per (b,c) sums ------------------------
__global__ void k_chansum(const float* __restrict__ x) {
    int c = blockIdx.x & 63, b = blockIdx.x >> 6;
    int tid = threadIdx.x;   // 256
    const float4* p = (const float4*)(x + (size_t)(b * 64 + c) * 16384);
    float s0 = 0.f, s1 = 0.f, s2 = 0.f, s3 = 0.f;
    #pragma unroll
    for (int i = 0; i < 16; ++i) {
        float4 v = p[tid + i * 256];
        s0 += v.x; s1 += v.y; s2 += v.z; s3 += v.w;
    }
    float s = (s0 + s1) + (s2 + s3);
    __shared__ float sh[256];
    sh[tid] = s;
    __syncthreads();
    for (int o = 128; o > 0; o >>= 1) {
        if (tid < o) sh[tid] += sh[tid + o];
        __syncthreads();
    }
    if (tid == 0) g_part[b * 64 + c] = sh[0];
}

// ---------------- weights: compose 1x1 into 5x5 (fp16) + bias ---------------
__global__ void k_weights(const float* __restrict__ w1, const float* __restrict__ b1,
                          const float* __restrict__ w2) {
    int blk = blockIdx.x, tid = threadIdx.x;   // 256
    if (blk < 50) {
        int idx = blk * 256 + tid;   // 0..12799
        int c = idx / 200, rem = idx % 200;
        int tap = rem / 8, slot = rem % 8;
        float f0 = 0.f, f1 = 0.f;
        if (slot < 5) {
            int k0 = (slot < 4) ? 2 * slot : 8;
            int k1 = (slot < 4) ? 2 * slot + 1 : 8;
            #pragma unroll 8
            for (int o = 0; o < 64; ++o) {
                float wo = w1[o * 64 + c];
                f0 += w2[(k0 * 64 + o) * 25 + tap] * wo;
                f1 += w2[(k1 * 64 + o) * 25 + tap] * wo;
            }
        }
        __half2 h = __floats2half2_rn(f0, f1);   // low = f0 (even k)
        g_Wh[idx] = *reinterpret_cast<uint32_t*>(&h);
    } else {
        if (tid < 225) {
            int k = tid / 25, tap = tid % 25;
            float s = 0.f;
            #pragma unroll 8
            for (int o = 0; o < 64; ++o)
                s += w2[(k * 64 + o) * 25 + tap] * b1[o];
            g_bc[tid] = s;
        }
    }
}

// ---------------- prep2: single block: bias case table + MLP ----------------
__global__ void k_prep2(const float* __restrict__ tc1, const float* __restrict__ tc2) {
    __shared__ float smean[64];
    __shared__ float sh1[16];
    int tid = threadIdx.x;   // 256
    if (tid < 64) {
        float s = 0.f;
        #pragma unroll
        for (int b = 0; b < 8; ++b) s += g_part[b * 64 + tid];
        smean[tid] = s * (1.f / 131072.f);
    }
    if (tid < 225) {
        int k = tid / 25, r = tid % 25;
        int a = r / 5, bb = r % 5;
        int ylo = (2 - a > 0) ? 2 - a : 0, yhi = (6 - a < 4) ? 6 - a : 4;
        int xlo = (2 - bb > 0) ? 2 - bb : 0, xhi = (6 - bb < 4) ? 6 - bb : 4;
        float s = 0.f;
        for (int dy = ylo; dy <= yhi; ++dy)
            for (int dx = xlo; dx <= xhi; ++dx)
                s += g_bc[k * 25 + dy * 5 + dx];
        g_B[tid] = s;
    }
    __syncthreads();
    if (tid < 16) {
        float a = 0.f;
        #pragma unroll
        for (int c = 0; c < 64; ++c) a += tc1[tid * 64 + c] * smean[c];
        sh1[tid] = fmaxf(a, 0.f);
    }
    __syncthreads();
    if (tid < 64) {
        float a = 0.f;
        #pragma unroll
        for (int j = 0; j < 16; ++j) a += tc2[tid * 16 + j] * sh1[j];
        g_t[tid] = fmaxf(a, 0.f) * LOG2E;
    }
}

// ---------------- conv: HFMA2, 32x16 tiles, double buffered, batch half -----
// Grid (4,8,4); block (32,4); thread owns 4 consecutive rows (ty*4+j), col tx.
// Dynamic smem (58880 B): sW[2][1600] u32; sX[2][5760] u32 (8c x 20 x 36).
// Staging uses structured (tx,ty) indexing: no integer division.
__global__ void __launch_bounds__(128) k_conv(const float* __restrict__ x, int bofs) {
    extern __shared__ uint32_t sdyn[];
    uint32_t* sWs = sdyn;            // 2 x 1600
    uint32_t* sXs = sdyn + 3200;     // 2 x 5760
    __shared__ float sB[225];
    int tx = threadIdx.x, ty = threadIdx.y;
    int tid = ty * 32 + tx;
    int h0 = blockIdx.y * 16, w0 = blockIdx.x * 32;
    int bz = blockIdx.z + bofs;
    const float* xb = x + (size_t)bz * 64 * 16384;

    for (int i = tid; i < 225; i += 128) sB[i] = g_B[i];

    __half2 acc[4][4], acc8[2];
    #pragma unroll
    for (int j = 0; j < 4; ++j)
        #pragma unroll
        for (int p = 0; p < 4; ++p) acc[j][p] = __floats2half2_rn(0.f, 0.f);
    acc8[0] = acc8[1] = __floats2half2_rn(0.f, 0.f);

    // structured staging of chunk cb into buffer buf (no int division)
    #define STAGE(buf, cb) do {                                                  \
        _Pragma("unroll")                                                        \
        for (int it = 0; it < 12; ++it)                                          \
            sWs[(buf) * 1600 + tid + it * 128] = g_Wh[(cb) * 200 + tid + it * 128]; \
        if (tid < 64)                                                            \
            sWs[(buf) * 1600 + 1536 + tid] = g_Wh[(cb) * 200 + 1536 + tid];      \
        _Pragma("unroll")                                                        \
        for (int c = 0; c < 8; ++c) {                                            \
            const float* xc = xb + (size_t)((cb) + c) * 16384;                   \
            _Pragma("unroll")                                                    \
            for (int rr = 0; rr < 5; ++rr) {                                     \
                int r = ty * 5 + rr;                                             \
                int gh = h0 + r - 2;                                             \
                bool okh = (gh >= 0) && (gh < 128);                              \
                int gw = w0 + tx - 2;                                            \
                float v = (okh && gw >= 0 && gw < 128) ? xc[gh * 128 + gw] : 0.f;\
                __half2 hv = __float2half2_rn(v);                                \
                sXs[(buf) * 5760 + c * 720 + r * 36 + tx] =                      \
                    *reinterpret_cast<uint32_t*>(&hv);                           \
                if (tx < 4) {                                                    \
                    int gw2 = gw + 32;                                           \
                    float v2 = (okh && gw2 < 128) ? xc[gh * 128 + gw2] : 0.f;    \
                    __half2 hv2 = __float2half2_rn(v2);                          \
                    sXs[(buf) * 5760 + c * 720 + r * 36 + tx + 32] =             \
                        *reinterpret_cast<uint32_t*>(&hv2);                      \
                }                                                                \
            }                                                                    \
        }                                                                        \
    } while (0)

    STAGE(0, 0);
    __syncthreads();

    #pragma unroll 1
    for (int ch = 0; ch < 8; ++ch) {
        int cur = ch & 1;
        if (ch < 7) {
            STAGE(cur ^ 1, (ch + 1) * 8);
        }
        #pragma unroll 1
        for (int c = 0; c < 8; ++c) {
            const uint32_t* xbase = sXs + cur * 5760 + c * 720 + (ty * 4) * 36 + tx;
            uint32_t xw[8][5];
            #pragma unroll
            for (int r = 0; r < 8; ++r)
                #pragma unroll
                for (int q = 0; q < 5; ++q)
                    xw[r][q] = xbase[r * 36 + q];

            const uint32_t* wc = sWs + cur * 1600 + c * 200;
            #pragma unroll
            for (int dy = 0; dy < 5; ++dy) {
                #pragma unroll
                for (int dx = 0; dx < 5; ++dx) {
                    int tap = dy * 5 + dx;
                    uint4 wv = *reinterpret_cast<const uint4*>(wc + tap * 8);
                    uint32_t p4 = wc[tap * 8 + 4];
                    __half2 w0h = u2h(wv.x), w1h = u2h(wv.y),
                            w2h = u2h(wv.z), w3h = u2h(wv.w);
                    #pragma unroll
                    for (int jp = 0; jp < 2; ++jp) {
                        uint32_t xa = xw[2 * jp + dy][dx];
                        uint32_t xb2 = xw[2 * jp + 1 + dy][dx];
                        __half2 ha = u2h(xa), hb = u2h(xb2);
                        acc[2 * jp][0] = __hfma2(w0h, ha, acc[2 * jp][0]);
                        acc[2 * jp][1] = __hfma2(w1h, ha, acc[2 * jp][1]);
                        acc[2 * jp][2] = __hfma2(w2h, ha, acc[2 * jp][2]);
                        acc[2 * jp][3] = __hfma2(w3h, ha, acc[2 * jp][3]);
                        acc[2 * jp + 1][0] = __hfma2(w0h, hb, acc[2 * jp + 1][0]);
                        acc[2 * jp + 1][1] = __hfma2(w1h, hb, acc[2 * jp + 1][1]);
                        acc[2 * jp + 1][2] = __hfma2(w2h, hb, acc[2 * jp + 1][2]);
                        acc[2 * jp + 1][3] = __hfma2(w3h, hb, acc[2 * jp + 1][3]);
                        uint32_t xab = __byte_perm(xa, xb2, 0x5410);   // {a.lo, b.lo}
                        acc8[jp] = __hfma2(u2h(p4), u2h(xab), acc8[jp]);
                    }
                }
            }
        }
        __syncthreads();
    }

    int w = w0 + tx;
    int cw = (w < 2) ? w : ((w > 125) ? (w - 123) : 2);
    #pragma unroll
    for (int j = 0; j < 4; ++j) {
        int h = h0 + ty * 4 + j;
        int pix = h * 128 + w;
        int chc = (h < 2) ? h : ((h > 125) ? (h - 123) : 2);
        float v[9];
        #pragma unroll
        for (int p = 0; p < 4; ++p) {
            v[2 * p]     = __low2float(acc[j][p]);
            v[2 * p + 1] = __high2float(acc[j][p]);
        }
        v[8] = (j & 1) ? __high2float(acc8[j >> 1]) : __low2float(acc8[j >> 1]);
        #pragma unroll
        for (int k = 0; k < 9; ++k)
            g_wt[((size_t)bz * 9 + k) * 16384 + pix] = v[k] + sB[k * 25 + chc * 5 + cw];
    }
    #undef STAGE
}

// ---------------- k_out: softmax + gather, smem-staged patches, batch half --
// Grid (64, 4, 8): (row pair, batch-in-half, channel eighth). 128 thr, 2 px.
__global__ void __launch_bounds__(128) k_out(const float* __restrict__ x,
                                             float* __restrict__ out, int bofs) {
    __shared__ float st[64];
    __shared__ float sx[2][4][132];
    int w = threadIdx.x;
    int h = blockIdx.x * 2;
    int b = blockIdx.y + bofs;
    int ce = blockIdx.z;
    if (w < 64) st[w] = g_t[w];

    int rows4[4];
    rows4[0] = (h == 0) ? 1 : h - 1;
    rows4[1] = h;
    rows4[2] = h + 1;
    rows4[3] = (h + 1 == 127) ? 126 : h + 2;

    float ak0[9], ak1[9];
    float M0 = -1e30f, M1 = -1e30f;
    #pragma unroll
    for (int k = 0; k < 9; ++k) {
        size_t i0 = ((size_t)b * 9 + k) * 16384 + h * 128 + w;
        float a0 = g_wt[i0], a1 = g_wt[i0 + 128];
        ak0[k] = a0; M0 = fmaxf(M0, a0);
        ak1[k] = a1; M1 = fmaxf(M1, a1);
    }
    #pragma unroll
    for (int k = 0; k < 9; ++k) { ak0[k] -= M0; ak1[k] -= M1; }

    const float* xb = x + (size_t)b * 64 * 16384;
    int cbeg = ce * 8;

    {
        const float* xc = xb + (size_t)cbeg * 16384;
        #pragma unroll
        for (int r = 0; r < 4; ++r) sx[0][r][w + 1] = xc[rows4[r] * 128 + w];
        if (w < 4) sx[0][w][0] = xc[rows4[w] * 128 + 1];
        else if (w < 8) sx[0][w - 4][129] = xc[rows4[w - 4] * 128 + 126];
    }
    __syncthreads();

    #pragma unroll 1
    for (int i = 0; i < 8; ++i) {
        int cur = i & 1;
        if (i < 7) {
            const float* xc = xb + (size_t)(cbeg + i + 1) * 16384;
            int nb = cur ^ 1;
            #pragma unroll
            for (int r = 0; r < 4; ++r) sx[nb][r][w + 1] = xc[rows4[r] * 128 + w];
            if (w < 4) sx[nb][w][0] = xc[rows4[w] * 128 + 1];
            else if (w < 8) sx[nb][w - 4][129] = xc[rows4[w - 4] * 128 + 126];
        }
        int c = cbeg + i;
        float t = st[c];
        float g[4][3];
        #pragma unroll
        for (int r = 0; r < 4; ++r) {
            g[r][0] = sx[cur][r][w];
            g[r][1] = sx[cur][r][w + 1];
            g[r][2] = sx[cur][r][w + 2];
        }
        float o0, o1;
        if (t == 0.f) {
            float sA = (g[0][0] + g[0][1]) + g[0][2];
            float sB2 = (g[1][0] + g[1][1]) + g[1][2];
            float sC = (g[2][0] + g[2][1]) + g[2][2];
            float sD = (g[3][0] + g[3][1]) + g[3][2];
            o0 = (sA + sB2 + sC) * (1.f / 9.f);
            o1 = (sB2 + sC + sD) * (1.f / 9.f);
        } else {
            float s0 = 0.f, oo0 = 0.f, s1 = 0.f, oo1 = 0.f;
            #pragma unroll
            for (int k = 0; k < 9; ++k) {
                float e0, e1;
                asm("ex2.approx.ftz.f32 %0, %1;" : "=f"(e0) : "f"(ak0[k] * t));
                asm("ex2.approx.ftz.f32 %0, %1;" : "=f"(e1) : "f"(ak1[k] * t));
                s0 += e0; oo0 = fmaf(e0, g[k / 3][k % 3], oo0);
                s1 += e1; oo1 = fmaf(e1, g[k / 3 + 1][k % 3], oo1);
            }
            o0 = __fdividef(oo0, s0);
            o1 = __fdividef(oo1, s1);
        }
        size_t obase = (size_t)(b * 64 + c) * 16384 + h * 128 + w;
        out[obase] = o0;
        out[obase + 128] = o1;
        __syncthreads();
    }
}

// ---------------- launch: fork-join two streams under graph capture ---------
extern "C" void kernel_launch(void* const* d_in, const int* in_sizes, int n_in,
                              void* d_out, int out_size) {
    const float* x   = (const float*)d_in[0];
    const float* w1  = (const float*)d_in[1];
    const float* b1  = (const float*)d_in[2];
    const float* w2  = (const float*)d_in[3];
    const float* tc1 = (const float*)d_in[4];
    const float* tc2 = (const float*)d_in[5];
    float* out = (float*)d_out;
    (void)in_sizes; (void)n_in; (void)out_size;

    static cudaStream_t sA = nullptr, sB = nullptr;
    static cudaEvent_t eFork, eW, eC1, ePrep, eA, eB;
    if (!sA) {
        cudaStreamCreateWithFlags(&sA, cudaStreamNonBlocking);
        cudaStreamCreateWithFlags(&sB, cudaStreamNonBlocking);
        cudaEventCreateWithFlags(&eFork, cudaEventDisableTiming);
        cudaEventCreateWithFlags(&eW, cudaEventDisableTiming);
        cudaEventCreateWithFlags(&eC1, cudaEventDisableTiming);
        cudaEventCreateWithFlags(&ePrep, cudaEventDisableTiming);
        cudaEventCreateWithFlags(&eA, cudaEventDisableTiming);
        cudaEventCreateWithFlags(&eB, cudaEventDisableTiming);
        cudaFuncSetAttribute(k_conv, cudaFuncAttributeMaxDynamicSharedMemorySize, 58880);
    }

    // fork from the (captured) base stream
    cudaEventRecord(eFork, 0);
    cudaStreamWaitEvent(sA, eFork, 0);
    cudaStreamWaitEvent(sB, eFork, 0);

    // stream A: weights -> conv half1 -> conv half2 -> k_out half2
    k_weights<<<51, 256, 0, sA>>>(w1, b1, w2);
    cudaEventRecord(eW, sA);

    // stream B: chansum || weights; then prep2 (needs g_bc)
    k_chansum<<<512, 256, 0, sB>>>(x);
    cudaStreamWaitEvent(sB, eW, 0);
    k_prep2<<<1, 256, 0, sB>>>(tc1, tc2);
    cudaEventRecord(ePrep, sB);

    dim3 gc(4, 8, 4), bc(32, 4);
    k_conv<<<gc, bc, 58880, sA>>>(x, 0);
    cudaEventRecord(eC1, sA);
    k_conv<<<gc, bc, 58880, sA>>>(x, 4);

    // stream B: k_out half1 overlaps conv half2
    cudaStreamWaitEvent(sB, eC1, 0);
    dim3 ge(64, 4, 8);
    k_out<<<ge, 128, 0, sB>>>(x, out, 0);

    // stream A: k_out half2 (needs prep2 result too)
    cudaStreamWaitEvent(sA, ePrep, 0);
    k_out<<<ge, 128, 0, sA>>>(x, out, 4);

    // join back to base stream
    cudaEventRecord(eA, sA);
    cudaEventRecord(eB, sB);
    cudaStreamWaitEvent(0, eA, 0);
    cudaStreamWaitEvent(0, eB, 0);
}

// round 15
// speedup vs baseline: 1.7114x; 1.7114x over previous
#include <cuda_runtime.h>
#include <cuda_fp16.h>
#include <cstdint>

#define LOG2E 1.4426950408889634f

// ---------------- scratch (device globals; no allocations allowed) ----------
__device__ float    g_part[8 * 64];           // per (b,c) partial sums
__device__ float    g_t[64];                  // relu(MLP) * log2(e)
__device__ uint32_t g_Wh[64 * 25 * 8];        // half2 weights [c][tap][8 slots]
__device__ float    g_bc[9 * 25];             // per-tap bias [k][tap]
__device__ float    g_B[225];                 // bias case table [k][hcase][wcase]
__device__ float    g_wt[8 * 9 * 128 * 128];  // conv logits [b][k][h][w]

__device__ __forceinline__ __half2 u2h(uint32_t u) {
    return *reinterpret_cast<__half2*>(&u);
}

// ---------------- P1: chansum (0..511) + weights (512..561) + bias (562) ----
__global__ void k_prep1(const float* __restrict__ x, const float* __restrict__ w1,
                        const float* __restrict__ b1, const float* __restrict__ w2) {
    int blk = blockIdx.x;
    int tid = threadIdx.x;   // 256
    if (blk < 512) {
        int c = blk & 63, b = blk >> 6;
        const float4* p = (const float4*)(x + (size_t)(b * 64 + c) * 16384);
        float s0 = 0.f, s1 = 0.f, s2 = 0.f, s3 = 0.f;
        #pragma unroll
        for (int i = 0; i < 16; ++i) {
            float4 v = p[tid + i * 256];
            s0 += v.x; s1 += v.y; s2 += v.z; s3 += v.w;
        }
        float s = (s0 + s1) + (s2 + s3);
        __shared__ float sh[256];
        sh[tid] = s;
        __syncthreads();
        for (int o = 128; o > 0; o >>= 1) {
            if (tid < o) sh[tid] += sh[tid + o];
            __syncthreads();
        }
        if (tid == 0) g_part[b * 64 + c] = sh[0];
    } else if (blk < 562) {
        int idx = (blk - 512) * 256 + tid;       // 0..12799
        if (idx < 12800) {
            int c = idx / 200, rem = idx % 200;
            int tap = rem / 8, slot = rem % 8;
            float f0 = 0.f, f1 = 0.f;
            if (slot < 5) {
                int k0 = (slot < 4) ? 2 * slot : 8;
                int k1 = (slot < 4) ? 2 * slot + 1 : 8;
                #pragma unroll 8
                for (int o = 0; o < 64; ++o) {
                    float wo = w1[o * 64 + c];
                    f0 += w2[(k0 * 64 + o) * 25 + tap] * wo;
                    f1 += w2[(k1 * 64 + o) * 25 + tap] * wo;
                }
            }
            __half2 h = __floats2half2_rn(f0, f1);   // low = f0 (even k)
            g_Wh[idx] = *reinterpret_cast<uint32_t*>(&h);
        }
    } else {
        if (tid < 225) {
            int k = tid / 25, tap = tid % 25;
            float s = 0.f;
            #pragma unroll 8
            for (int o = 0; o < 64; ++o)
                s += w2[(k * 64 + o) * 25 + tap] * b1[o];
            g_bc[tid] = s;
        }
    }
}

// ---------------- P2: single block: bias case table + MLP -------------------
__global__ void k_prep2(const float* __restrict__ tc1, const float* __restrict__ tc2) {
    __shared__ float smean[64];
    __shared__ float sh1[16];
    int tid = threadIdx.x;   // 256
    if (tid < 64) {
        float s = 0.f;
        #pragma unroll
        for (int b = 0; b < 8; ++b) s += g_part[b * 64 + tid];
        smean[tid] = s * (1.f / 131072.f);
    }
    if (tid < 225) {
        int k = tid / 25, r = tid % 25;
        int a = r / 5, bb = r % 5;
        int ylo = (2 - a > 0) ? 2 - a : 0, yhi = (6 - a < 4) ? 6 - a : 4;
        int xlo = (2 - bb > 0) ? 2 - bb : 0, xhi = (6 - bb < 4) ? 6 - bb : 4;
        float s = 0.f;
        for (int dy = ylo; dy <= yhi; ++dy)
            for (int dx = xlo; dx <= xhi; ++dx)
                s += g_bc[k * 25 + dy * 5 + dx];
        g_B[tid] = s;
    }
    __syncthreads();
    if (tid < 16) {
        float a = 0.f;
        #pragma unroll
        for (int c = 0; c < 64; ++c) a += tc1[tid * 64 + c] * smean[c];
        sh1[tid] = fmaxf(a, 0.f);
    }
    __syncthreads();
    if (tid < 64) {
        float a = 0.f;
        #pragma unroll
        for (int j = 0; j < 16; ++j) a += tc2[tid * 16 + j] * sh1[j];
        g_t[tid] = fmaxf(a, 0.f) * LOG2E;
    }
}

// ---------------- conv: HFMA2, 32x16 tiles, double buffered -----------------
// Grid (4,8,8) = 256 CTAs; block (32,4); thread owns 4 consecutive rows, col tx.
// Dynamic smem (58880 B): sW[2][1600] u32; sX[2][5760] u32 (8c x 20 x 36).
// Staging uses structured (tx,ty) indexing: no integer division.
__global__ void __launch_bounds__(128) k_conv(const float* __restrict__ x) {
    extern __shared__ uint32_t sdyn[];
    uint32_t* sWs = sdyn;            // 2 x 1600
    uint32_t* sXs = sdyn + 3200;     // 2 x 5760
    __shared__ float sB[225];
    int tx = threadIdx.x, ty = threadIdx.y;
    int tid = ty * 32 + tx;
    int h0 = blockIdx.y * 16, w0 = blockIdx.x * 32;
    int bz = blockIdx.z;
    const float* xb = x + (size_t)bz * 64 * 16384;

    for (int i = tid; i < 225; i += 128) sB[i] = g_B[i];

    __half2 acc[4][4], acc8[2];
    #pragma unroll
    for (int j = 0; j < 4; ++j)
        #pragma unroll
        for (int p = 0; p < 4; ++p) acc[j][p] = __floats2half2_rn(0.f, 0.f);
    acc8[0] = acc8[1] = __floats2half2_rn(0.f, 0.f);

    // structured staging of chunk cb into buffer buf (no int division)
    #define STAGE(buf, cb) do {                                                  \
        _Pragma("unroll")                                                        \
        for (int it = 0; it < 12; ++it)                                          \
            sWs[(buf) * 1600 + tid + it * 128] = g_Wh[(cb) * 200 + tid + it * 128]; \
        if (tid < 64)                                                            \
            sWs[(buf) * 1600 + 1536 + tid] = g_Wh[(cb) * 200 + 1536 + tid];      \
        _Pragma("unroll")                                                        \
        for (int c = 0; c < 8; ++c) {                                            \
            const float* xc = xb + (size_t)((cb) + c) * 16384;                   \
            _Pragma("unroll")                                                    \
            for (int rr = 0; rr < 5; ++rr) {                                     \
                int r = ty * 5 + rr;                                             \
                int gh = h0 + r - 2;                                             \
                bool okh = (gh >= 0) && (gh < 128);                              \
                int gw = w0 + tx - 2;                                            \
                float v = (okh && gw >= 0 && gw < 128) ? xc[gh * 128 + gw] : 0.f;\
                __half2 hv = __float2half2_rn(v);                                \
                sXs[(buf) * 5760 + c * 720 + r * 36 + tx] =                      \
                    *reinterpret_cast<uint32_t*>(&hv);                           \
                if (tx < 4) {                                                    \
                    int gw2 = gw + 32;                                           \
                    float v2 = (okh && gw2 < 128) ? xc[gh * 128 + gw2] : 0.f;    \
                    __half2 hv2 = __float2half2_rn(v2);                          \
                    sXs[(buf) * 5760 + c * 720 + r * 36 + tx + 32] =             \
                        *reinterpret_cast<uint32_t*>(&hv2);                      \
                }                                                                \
            }                                                                    \
        }                                                                        \
    } while (0)

    STAGE(0, 0);
    __syncthreads();

    #pragma unroll 1
    for (int ch = 0; ch < 8; ++ch) {
        int cur = ch & 1;
        if (ch < 7) {
            STAGE(cur ^ 1, (ch + 1) * 8);
        }
        #pragma unroll 1
        for (int c = 0; c < 8; ++c) {
            const uint32_t* xbase = sXs + cur * 5760 + c * 720 + (ty * 4) * 36 + tx;
            uint32_t xw[8][5];
            #pragma unroll
            for (int r = 0; r < 8; ++r)
                #pragma unroll
                for (int q = 0; q < 5; ++q)
                    xw[r][q] = xbase[r * 36 + q];

            const uint32_t* wc = sWs + cur * 1600 + c * 200;
            #pragma unroll
            for (int dy = 0; dy < 5; ++dy) {
                #pragma unroll
                for (int dx = 0; dx < 5; ++dx) {
                    int tap = dy * 5 + dx;
                    uint4 wv = *reinterpret_cast<const uint4*>(wc + tap * 8);
                    uint32_t p4 = wc[tap * 8 + 4];
                    __half2 w0h = u2h(wv.x), w1h = u2h(wv.y),
                            w2h = u2h(wv.z), w3h = u2h(wv.w);
                    #pragma unroll
                    for (int jp = 0; jp < 2; ++jp) {
                        uint32_t xa = xw[2 * jp + dy][dx];
                        uint32_t xb2 = xw[2 * jp + 1 + dy][dx];
                        __half2 ha = u2h(xa), hb = u2h(xb2);
                        acc[2 * jp][0] = __hfma2(w0h, ha, acc[2 * jp][0]);
                        acc[2 * jp][1] = __hfma2(w1h, ha, acc[2 * jp][1]);
                        acc[2 * jp][2] = __hfma2(w2h, ha, acc[2 * jp][2]);
                        acc[2 * jp][3] = __hfma2(w3h, ha, acc[2 * jp][3]);
                        acc[2 * jp + 1][0] = __hfma2(w0h, hb, acc[2 * jp + 1][0]);
                        acc[2 * jp + 1][1] = __hfma2(w1h, hb, acc[2 * jp + 1][1]);
                        acc[2 * jp + 1][2] = __hfma2(w2h, hb, acc[2 * jp + 1][2]);
                        acc[2 * jp + 1][3] = __hfma2(w3h, hb, acc[2 * jp + 1][3]);
                        uint32_t xab = __byte_perm(xa, xb2, 0x5410);   // {a.lo, b.lo}
                        acc8[jp] = __hfma2(u2h(p4), u2h(xab), acc8[jp]);
                    }
                }
            }
        }
        __syncthreads();
    }

    int w = w0 + tx;
    int cw = (w < 2) ? w : ((w > 125) ? (w - 123) : 2);
    #pragma unroll
    for (int j = 0; j < 4; ++j) {
        int h = h0 + ty * 4 + j;
        int pix = h * 128 + w;
        int chc = (h < 2) ? h : ((h > 125) ? (h - 123) : 2);
        float v[9];
        #pragma unroll
        for (int p = 0; p < 4; ++p) {
            v[2 * p]     = __low2float(acc[j][p]);
            v[2 * p + 1] = __high2float(acc[j][p]);
        }
        v[8] = (j & 1) ? __high2float(acc8[j >> 1]) : __low2float(acc8[j >> 1]);
        #pragma unroll
        for (int k = 0; k < 9; ++k)
            g_wt[((size_t)bz * 9 + k) * 16384 + pix] = v[k] + sB[k * 25 + chc * 5 + cw];
    }
    #undef STAGE
}

// ---------------- k_out: softmax(wt_k * t_c) * 3x3 reflect patches ----------
// Grid (64, 8, 8): (row pair, batch, channel eighth). 128 threads, 2 px each.
__global__ void __launch_bounds__(128) k_out(const float* __restrict__ x,
                                             float* __restrict__ out) {
    __shared__ float st[64];
    int w = threadIdx.x;
    int h = blockIdx.x * 2;
    int b = blockIdx.y;
    int ce = blockIdx.z;
    if (w < 64) st[w] = g_t[w];
    __syncthreads();

    int rm = (h == 0) ? 1 : h - 1;
    int r1 = h, r2 = h + 1;
    int rp = (h + 1 == 127) ? 126 : h + 2;
    int wm = (w == 0) ? 1 : w - 1;
    int wp = (w == 127) ? 126 : w + 1;

    float ak0[9], ak1[9];
    float M0 = -1e30f, M1 = -1e30f;
    #pragma unroll
    for (int k = 0; k < 9; ++k) {
        size_t i0 = ((size_t)b * 9 + k) * 16384 + r1 * 128 + w;
        float a0 = g_wt[i0], a1 = g_wt[i0 + 128];
        ak0[k] = a0; M0 = fmaxf(M0, a0);
        ak1[k] = a1; M1 = fmaxf(M1, a1);
    }
    #pragma unroll
    for (int k = 0; k < 9; ++k) { ak0[k] -= M0; ak1[k] -= M1; }

    const float* xb = x + (size_t)b * 64 * 16384;
    int cbeg = ce * 8;
    #pragma unroll 2
    for (int c = cbeg; c < cbeg + 8; ++c) {
        const float* xc = xb + (size_t)c * 16384;
        float t = st[c];
        float g[4][3];
        g[0][0] = xc[rm * 128 + wm]; g[0][1] = xc[rm * 128 + w]; g[0][2] = xc[rm * 128 + wp];
        g[1][0] = xc[r1 * 128 + wm]; g[1][1] = xc[r1 * 128 + w]; g[1][2] = xc[r1 * 128 + wp];
        g[2][0] = xc[r2 * 128 + wm]; g[2][1] = xc[r2 * 128 + w]; g[2][2] = xc[r2 * 128 + wp];
        g[3][0] = xc[rp * 128 + wm]; g[3][1] = xc[rp * 128 + w]; g[3][2] = xc[rp * 128 + wp];
        float o0, o1;
        if (t == 0.f) {
            float sA = (g[0][0] + g[0][1]) + g[0][2];
            float sB2 = (g[1][0] + g[1][1]) + g[1][2];
            float sC = (g[2][0] + g[2][1]) + g[2][2];
            float sD = (g[3][0] + g[3][1]) + g[3][2];
            o0 = (sA + sB2 + sC) * (1.f / 9.f);
            o1 = (sB2 + sC + sD) * (1.f / 9.f);
        } else {
            float s0 = 0.f, oo0 = 0.f, s1 = 0.f, oo1 = 0.f;
            #pragma unroll
            for (int k = 0; k < 9; ++k) {
                float e0, e1;
                asm("ex2.approx.ftz.f32 %0, %1;" : "=f"(e0) : "f"(ak0[k] * t));
                asm("ex2.approx.ftz.f32 %0, %1;" : "=f"(e1) : "f"(ak1[k] * t));
                s0 += e0; oo0 = fmaf(e0, g[k / 3][k % 3], oo0);
                s1 += e1; oo1 = fmaf(e1, g[k / 3 + 1][k % 3], oo1);
            }
            o0 = __fdividef(oo0, s0);
            o1 = __fdividef(oo1, s1);
        }
        size_t obase = (size_t)(b * 64 + c) * 16384 + r1 * 128 + w;
        out[obase] = o0;
        out[obase + 128] = o1;
    }
}

// ---------------- launch ----------------------------------------------------
extern "C" void kernel_launch(void* const* d_in, const int* in_sizes, int n_in,
                              void* d_out, int out_size) {
    const float* x   = (const float*)d_in[0];
    const float* w1  = (const float*)d_in[1];
    const float* b1  = (const float*)d_in[2];
    const float* w2  = (const float*)d_in[3];
    const float* tc1 = (const float*)d_in[4];
    const float* tc2 = (const float*)d_in[5];
    float* out = (float*)d_out;
    (void)in_sizes; (void)n_in; (void)out_size;

    static bool attr_set = false;
    if (!attr_set) {
        cudaFuncSetAttribute(k_conv, cudaFuncAttributeMaxDynamicSharedMemorySize, 58880);
        attr_set = true;
    }

    k_prep1<<<563, 256>>>(x, w1, b1, w2);
    k_prep2<<<1, 256>>>(tc1, tc2);
    dim3 gc(4, 8, 8), bc(32, 4);
    k_conv<<<gc, bc, 58880>>>(x);
    dim3 ge(64, 8, 8);
    k_out<<<ge, 128>>>(x, out);
}

// round 16
// speedup vs baseline: 2.7306x; 1.5955x over previous
#include <cuda_runtime.h>
#include <cuda_fp16.h>
#include <cstdint>

#define LOG2E 1.4426950408889634f

// ---------------- scratch (device globals; no allocations allowed) ----------
__device__ float    g_part[8 * 64];           // per (b,c) partial sums
__device__ float    g_t[64];                  // relu(MLP) * log2(e)
__device__ uint32_t g_Wh[64 * 25 * 8];        // half2 weights [c][tap][8 slots]
__device__ float    g_bc[9 * 25];             // per-tap bias [k][tap]
__device__ float    g_B[225];                 // bias case table [k][hcase][wcase]
__device__ float    g_wt[8 * 9 * 128 * 128];  // conv logits [b][k][h][w]

__device__ __forceinline__ __half2 u2h(uint32_t u) {
    return *reinterpret_cast<__half2*>(&u);
}

// ---------------- P1: chansum (0..511) + weights (512..561) + bias (562) ----
__global__ void k_prep1(const float* __restrict__ x, const float* __restrict__ w1,
                        const float* __restrict__ b1, const float* __restrict__ w2) {
    int blk = blockIdx.x;
    int tid = threadIdx.x;   // 256
    if (blk < 512) {
        int c = blk & 63, b = blk >> 6;
        const float4* p = (const float4*)(x + (size_t)(b * 64 + c) * 16384);
        float s0 = 0.f, s1 = 0.f, s2 = 0.f, s3 = 0.f;
        #pragma unroll
        for (int i = 0; i < 16; ++i) {
            float4 v = p[tid + i * 256];
            s0 += v.x; s1 += v.y; s2 += v.z; s3 += v.w;
        }
        float s = (s0 + s1) + (s2 + s3);
        __shared__ float sh[256];
        sh[tid] = s;
        __syncthreads();
        for (int o = 128; o > 0; o >>= 1) {
            if (tid < o) sh[tid] += sh[tid + o];
            __syncthreads();
        }
        if (tid == 0) g_part[b * 64 + c] = sh[0];
    } else if (blk < 562) {
        int idx = (blk - 512) * 256 + tid;       // 0..12799
        if (idx < 12800) {
            int c = idx / 200, rem = idx % 200;
            int tap = rem / 8, slot = rem % 8;
            float f0 = 0.f, f1 = 0.f;
            if (slot < 5) {
                int k0 = (slot < 4) ? 2 * slot : 8;
                int k1 = (slot < 4) ? 2 * slot + 1 : 8;
                float f0a = 0.f, f0b = 0.f, f1a = 0.f, f1b = 0.f;
                #pragma unroll
                for (int o = 0; o < 64; o += 2) {
                    float woa = w1[o * 64 + c];
                    float wob = w1[(o + 1) * 64 + c];
                    f0a += w2[(k0 * 64 + o) * 25 + tap] * woa;
                    f0b += w2[(k0 * 64 + o + 1) * 25 + tap] * wob;
                    f1a += w2[(k1 * 64 + o) * 25 + tap] * woa;
                    f1b += w2[(k1 * 64 + o + 1) * 25 + tap] * wob;
                }
                f0 = f0a + f0b;
                f1 = f1a + f1b;
            }
            __half2 h = __floats2half2_rn(f0, f1);   // low = f0 (even k)
            g_Wh[idx] = *reinterpret_cast<uint32_t*>(&h);
        }
    } else {
        if (tid < 225) {
            int k = tid / 25, tap = tid % 25;
            float s = 0.f;
            #pragma unroll 8
            for (int o = 0; o < 64; ++o)
                s += w2[(k * 64 + o) * 25 + tap] * b1[o];
            g_bc[tid] = s;
        }
    }
}

// ---------------- P2: single block: bias case table + MLP -------------------
__global__ void k_prep2(const float* __restrict__ tc1, const float* __restrict__ tc2) {
    __shared__ float smean[64];
    __shared__ float sh1[16];
    int tid = threadIdx.x;   // 256
    if (tid < 64) {
        float s = 0.f;
        #pragma unroll
        for (int b = 0; b < 8; ++b) s += g_part[b * 64 + tid];
        smean[tid] = s * (1.f / 131072.f);
    }
    if (tid < 225) {
        int k = tid / 25, r = tid % 25;
        int a = r / 5, bb = r % 5;
        int ylo = (2 - a > 0) ? 2 - a : 0, yhi = (6 - a < 4) ? 6 - a : 4;
        int xlo = (2 - bb > 0) ? 2 - bb : 0, xhi = (6 - bb < 4) ? 6 - bb : 4;
        float s = 0.f;
        for (int dy = ylo; dy <= yhi; ++dy)
            for (int dx = xlo; dx <= xhi; ++dx)
                s += g_bc[k * 25 + dy * 5 + dx];
        g_B[tid] = s;
    }
    __syncthreads();
    if (tid < 16) {
        float a = 0.f;
        #pragma unroll
        for (int c = 0; c < 64; ++c) a += tc1[tid * 64 + c] * smean[c];
        sh1[tid] = fmaxf(a, 0.f);
    }
    __syncthreads();
    if (tid < 64) {
        float a = 0.f;
        #pragma unroll
        for (int j = 0; j < 16; ++j) a += tc2[tid * 16 + j] * sh1[j];
        g_t[tid] = fmaxf(a, 0.f) * LOG2E;
    }
}

// ---------------- conv: R11 verbatim (div staging, double buffer, 32x16) ----
// Grid (4,8,8) = 256 CTAs; block (32,4); thread owns 4 consecutive rows, col tx.
// Dynamic smem (58880 B): sW[2][1600] u32; sX[2][5760] u32 (8c x 20 x 36).
// Only change vs R11: epilogue bias from sB case table (g_bfield deleted).
__global__ void __launch_bounds__(128) k_conv(const float* __restrict__ x) {
    extern __shared__ uint32_t sdyn[];
    uint32_t* sWs = sdyn;            // 2 x 1600
    uint32_t* sXs = sdyn + 3200;     // 2 x 5760
    __shared__ float sB[225];
    int tx = threadIdx.x, ty = threadIdx.y;
    int tid = ty * 32 + tx;
    int h0 = blockIdx.y * 16, w0 = blockIdx.x * 32;
    int bz = blockIdx.z;
    const float* xb = x + (size_t)bz * 64 * 16384;

    for (int i = tid; i < 225; i += 128) sB[i] = g_B[i];

    __half2 acc[4][4], acc8[2];
    #pragma unroll
    for (int j = 0; j < 4; ++j)
        #pragma unroll
        for (int p = 0; p < 4; ++p) acc[j][p] = __floats2half2_rn(0.f, 0.f);
    acc8[0] = acc8[1] = __floats2half2_rn(0.f, 0.f);

    // --- stage chunk 0 into buffer 0 ---
    #pragma unroll
    for (int it = 0; it < 13; ++it) {
        int i = tid + it * 128;
        if (i < 1600) sWs[i] = g_Wh[i];
    }
    #pragma unroll
    for (int it = 0; it < 45; ++it) {
        int i = tid + it * 128;
        int c = i / 720, rem = i % 720;
        int y = rem / 36, xx = rem % 36;
        int gh = h0 + y - 2, gw = w0 + xx - 2;
        float v = 0.f;
        if (gh >= 0 && gh < 128 && gw >= 0 && gw < 128)
            v = xb[(size_t)c * 16384 + gh * 128 + gw];
        __half2 hv = __float2half2_rn(v);
        sXs[i] = *reinterpret_cast<uint32_t*>(&hv);
    }
    __syncthreads();

    #pragma unroll 1
    for (int ch = 0; ch < 8; ++ch) {
        int cur = ch & 1;
        if (ch < 7) {
            int nb = cur ^ 1;
            int cb = (ch + 1) * 8;
            #pragma unroll
            for (int it = 0; it < 13; ++it) {
                int i = tid + it * 128;
                if (i < 1600) sWs[nb * 1600 + i] = g_Wh[cb * 200 + i];
            }
            #pragma unroll
            for (int it = 0; it < 45; ++it) {
                int i = tid + it * 128;
                int c = i / 720, rem = i % 720;
                int y = rem / 36, xx = rem % 36;
                int gh = h0 + y - 2, gw = w0 + xx - 2;
                float v = 0.f;
                if (gh >= 0 && gh < 128 && gw >= 0 && gw < 128)
                    v = xb[(size_t)(cb + c) * 16384 + gh * 128 + gw];
                __half2 hv = __float2half2_rn(v);
                sXs[nb * 5760 + i] = *reinterpret_cast<uint32_t*>(&hv);
            }
        }
        #pragma unroll 1
        for (int c = 0; c < 8; ++c) {
            const uint32_t* xbase = sXs + cur * 5760 + c * 720 + (ty * 4) * 36 + tx;
            uint32_t xw[8][5];
            #pragma unroll
            for (int r = 0; r < 8; ++r)
                #pragma unroll
                for (int q = 0; q < 5; ++q)
                    xw[r][q] = xbase[r * 36 + q];

            const uint32_t* wc = sWs + cur * 1600 + c * 200;
            #pragma unroll
            for (int dy = 0; dy < 5; ++dy) {
                #pragma unroll
                for (int dx = 0; dx < 5; ++dx) {
                    int tap = dy * 5 + dx;
                    uint4 wv = *reinterpret_cast<const uint4*>(wc + tap * 8);
                    uint32_t p4 = wc[tap * 8 + 4];
                    __half2 w0h = u2h(wv.x), w1h = u2h(wv.y),
                            w2h = u2h(wv.z), w3h = u2h(wv.w);
                    #pragma unroll
                    for (int jp = 0; jp < 2; ++jp) {
                        uint32_t xa = xw[2 * jp + dy][dx];
                        uint32_t xb2 = xw[2 * jp + 1 + dy][dx];
                        __half2 ha = u2h(xa), hb = u2h(xb2);
                        acc[2 * jp][0] = __hfma2(w0h, ha, acc[2 * jp][0]);
                        acc[2 * jp][1] = __hfma2(w1h, ha, acc[2 * jp][1]);
                        acc[2 * jp][2] = __hfma2(w2h, ha, acc[2 * jp][2]);
                        acc[2 * jp][3] = __hfma2(w3h, ha, acc[2 * jp][3]);
                        acc[2 * jp + 1][0] = __hfma2(w0h, hb, acc[2 * jp + 1][0]);
                        acc[2 * jp + 1][1] = __hfma2(w1h, hb, acc[2 * jp + 1][1]);
                        acc[2 * jp + 1][2] = __hfma2(w2h, hb, acc[2 * jp + 1][2]);
                        acc[2 * jp + 1][3] = __hfma2(w3h, hb, acc[2 * jp + 1][3]);
                        uint32_t xab = __byte_perm(xa, xb2, 0x5410);   // {a.lo, b.lo}
                        acc8[jp] = __hfma2(u2h(p4), u2h(xab), acc8[jp]);
                    }
                }
            }
        }
        __syncthreads();
    }

    int w = w0 + tx;
    int cw = (w < 2) ? w : ((w > 125) ? (w - 123) : 2);
    #pragma unroll
    for (int j = 0; j < 4; ++j) {
        int h = h0 + ty * 4 + j;
        int pix = h * 128 + w;
        int chc = (h < 2) ? h : ((h > 125) ? (h - 123) : 2);
        float v[9];
        #pragma unroll
        for (int p = 0; p < 4; ++p) {
            v[2 * p]     = __low2float(acc[j][p]);
            v[2 * p + 1] = __high2float(acc[j][p]);
        }
        v[8] = (j & 1) ? __high2float(acc8[j >> 1]) : __low2float(acc8[j >> 1]);
        #pragma unroll
        for (int k = 0; k < 9; ++k)
            g_wt[((size_t)bz * 9 + k) * 16384 + pix] = v[k] + sB[k * 25 + chc * 5 + cw];
    }
}

// ---------------- k_out: R11 verbatim ---------------------------------------
// Grid (64, 8, 8): (row pair, batch, channel eighth). 128 threads, 2 px each.
__global__ void __launch_bounds__(128) k_out(const float* __restrict__ x,
                                             float* __restrict__ out) {
    __shared__ float st[64];
    int w = threadIdx.x;
    int h = blockIdx.x * 2;
    int b = blockIdx.y;
    int ce = blockIdx.z;
    if (w < 64) st[w] = g_t[w];
    __syncthreads();

    int rm = (h == 0) ? 1 : h - 1;
    int r1 = h, r2 = h + 1;
    int rp = (h + 1 == 127) ? 126 : h + 2;
    int wm = (w == 0) ? 1 : w - 1;
    int wp = (w == 127) ? 126 : w + 1;

    float ak0[9], ak1[9];
    float M0 = -1e30f, M1 = -1e30f;
    #pragma unroll
    for (int k = 0; k < 9; ++k) {
        size_t i0 = ((size_t)b * 9 + k) * 16384 + r1 * 128 + w;
        float a0 = g_wt[i0], a1 = g_wt[i0 + 128];
        ak0[k] = a0; M0 = fmaxf(M0, a0);
        ak1[k] = a1; M1 = fmaxf(M1, a1);
    }
    #pragma unroll
    for (int k = 0; k < 9; ++k) { ak0[k] -= M0; ak1[k] -= M1; }

    const float* xb = x + (size_t)b * 64 * 16384;
    int cbeg = ce * 8;
    #pragma unroll 2
    for (int c = cbeg; c < cbeg + 8; ++c) {
        const float* xc = xb + (size_t)c * 16384;
        float t = st[c];
        float g[4][3];
        g[0][0] = xc[rm * 128 + wm]; g[0][1] = xc[rm * 128 + w]; g[0][2] = xc[rm * 128 + wp];
        g[1][0] = xc[r1 * 128 + wm]; g[1][1] = xc[r1 * 128 + w]; g[1][2] = xc[r1 * 128 + wp];
        g[2][0] = xc[r2 * 128 + wm]; g[2][1] = xc[r2 * 128 + w]; g[2][2] = xc[r2 * 128 + wp];
        g[3][0] = xc[rp * 128 + wm]; g[3][1] = xc[rp * 128 + w]; g[3][2] = xc[rp * 128 + wp];
        float o0, o1;
        if (t == 0.f) {
            float sA = (g[0][0] + g[0][1]) + g[0][2];
            float sB2 = (g[1][0] + g[1][1]) + g[1][2];
            float sC = (g[2][0] + g[2][1]) + g[2][2];
            float sD = (g[3][0] + g[3][1]) + g[3][2];
            o0 = (sA + sB2 + sC) * (1.f / 9.f);
            o1 = (sB2 + sC + sD) * (1.f / 9.f);
        } else {
            float s0 = 0.f, oo0 = 0.f, s1 = 0.f, oo1 = 0.f;
            #pragma unroll
            for (int k = 0; k < 9; ++k) {
                float e0, e1;
                asm("ex2.approx.ftz.f32 %0, %1;" : "=f"(e0) : "f"(ak0[k] * t));
                asm("ex2.approx.ftz.f32 %0, %1;" : "=f"(e1) : "f"(ak1[k] * t));
                s0 += e0; oo0 = fmaf(e0, g[k / 3][k % 3], oo0);
                s1 += e1; oo1 = fmaf(e1, g[k / 3 + 1][k % 3], oo1);
            }
            o0 = __fdividef(oo0, s0);
            o1 = __fdividef(oo1, s1);
        }
        size_t obase = (size_t)(b * 64 + c) * 16384 + r1 * 128 + w;
        out[obase] = o0;
        out[obase + 128] = o1;
    }
}

// ---------------- launch ----------------------------------------------------
extern "C" void kernel_launch(void* const* d_in, const int* in_sizes, int n_in,
                              void* d_out, int out_size) {
    const float* x   = (const float*)d_in[0];
    const float* w1  = (const float*)d_in[1];
    const float* b1  = (const float*)d_in[2];
    const float* w2  = (const float*)d_in[3];
    const float* tc1 = (const float*)d_in[4];
    const float* tc2 = (const float*)d_in[5];
    float* out = (float*)d_out;
    (void)in_sizes; (void)n_in; (void)out_size;

    static bool attr_set = false;
    if (!attr_set) {
        cudaFuncSetAttribute(k_conv, cudaFuncAttributeMaxDynamicSharedMemorySize, 58880);
        attr_set = true;
    }

    k_prep1<<<563, 256>>>(x, w1, b1, w2);
    k_prep2<<<1, 256>>>(tc1, tc2);
    dim3 gc(4, 8, 8), bc(32, 4);
    k_conv<<<gc, bc, 58880>>>(x);
    dim3 ge(64, 8, 8);
    k_out<<<ge, 128>>>(x, out);
}